// round 2
// baseline (speedup 1.0000x reference)
#include <cuda_runtime.h>
#include <cuda_bf16.h>

#define T_LEN    2048
#define D_DIM    128
#define NQ_H     32
#define NKV_H    8
#define BM       64
#define BN       64
#define KSTRIDE  132   // padded row stride for Qs/Ks/Vs (floats), 16B-aligned rows
#define PSTRIDE  68    // padded row stride for Ps (floats), 16B-aligned rows
#define NTHREADS 256

__global__ __launch_bounds__(NTHREADS, 1)
void attn_fwd(const float* __restrict__ Q, const float* __restrict__ K,
              const float* __restrict__ V, const int* __restrict__ SEG,
              float* __restrict__ O)
{
    extern __shared__ float sm[];
    float* Qs = sm;                         // BM x KSTRIDE
    float* Ks = Qs + BM * KSTRIDE;          // BN x KSTRIDE
    float* Vs = Ks + BN * KSTRIDE;          // BN x KSTRIDE
    float* Ps = Vs + BN * KSTRIDE;          // BM x PSTRIDE
    int*   segKs = (int*)(Ps + BM * PSTRIDE);  // BN

    const int b   = blockIdx.z;
    const int qh  = blockIdx.y;
    const int kvh = qh >> 2;                // G = NQ/NKV = 4
    const int m0  = blockIdx.x * BM;

    const int tid = threadIdx.x;
    const int tx  = tid & 15;
    const int ty  = tid >> 4;

    const int* segB = SEG + b * T_LEN;

    // ---- Load Q tile [BM x D] ----
    const float* qbase = Q + ((size_t)(b * T_LEN + m0) * NQ_H + qh) * D_DIM;
    for (int i = tid; i < BM * (D_DIM / 4); i += NTHREADS) {
        int r = i >> 5, c4 = i & 31;        // 32 float4 per row
        *(float4*)(Qs + r * KSTRIDE + c4 * 4) =
            *(const float4*)(qbase + (size_t)r * NQ_H * D_DIM + c4 * 4);
    }

    int segq[4];
#pragma unroll
    for (int i = 0; i < 4; i++) segq[i] = segB[m0 + ty * 4 + i];
    const int segRowMin = segB[m0];
    const int segRowMax = segB[m0 + BM - 1];

    float m_i[4], l_i[4], acc[4][8];
#pragma unroll
    for (int i = 0; i < 4; i++) { m_i[i] = -1e30f; l_i[i] = 0.f; }
#pragma unroll
    for (int i = 0; i < 4; i++)
#pragma unroll
        for (int j = 0; j < 8; j++) acc[i][j] = 0.f;

    const int nTiles = m0 / BN + 1;         // causal bound
    const float* kbase0 = K + ((size_t)b * T_LEN * NKV_H + kvh) * D_DIM;
    const float* vbase0 = V + ((size_t)b * T_LEN * NKV_H + kvh) * D_DIM;

    for (int nt = 0; nt < nTiles; nt++) {
        const int n0 = nt * BN;

        // Uniform per-tile segment skip (seg ids sorted -> contiguous segments).
        const int scMin = segB[n0];
        const int scMax = segB[n0 + BN - 1];
        if (scMin > segRowMax || scMax < segRowMin) continue;  // fully masked

        __syncthreads();  // previous iteration's PV done before overwriting K/V
        for (int i = tid; i < BN * (D_DIM / 4); i += NTHREADS) {
            int r = i >> 5, c4 = i & 31;
            const float* kp = kbase0 + (size_t)(n0 + r) * NKV_H * D_DIM + c4 * 4;
            const float* vp = vbase0 + (size_t)(n0 + r) * NKV_H * D_DIM + c4 * 4;
            *(float4*)(Ks + r * KSTRIDE + c4 * 4) = *(const float4*)kp;
            *(float4*)(Vs + r * KSTRIDE + c4 * 4) = *(const float4*)vp;
        }
        if (tid < BN) segKs[tid] = segB[n0 + tid];
        __syncthreads();

        // ---- S = Q K^T : thread owns rows ty*4+i, cols tx*4+j ----
        float s[4][4];
#pragma unroll
        for (int i = 0; i < 4; i++)
#pragma unroll
            for (int j = 0; j < 4; j++) s[i][j] = 0.f;

#pragma unroll 4
        for (int k4 = 0; k4 < D_DIM / 4; k4++) {
            float4 qv[4], kv[4];
#pragma unroll
            for (int i = 0; i < 4; i++)
                qv[i] = *(float4*)(Qs + (ty * 4 + i) * KSTRIDE + k4 * 4);
#pragma unroll
            for (int j = 0; j < 4; j++)
                kv[j] = *(float4*)(Ks + (tx * 4 + j) * KSTRIDE + k4 * 4);
#pragma unroll
            for (int i = 0; i < 4; i++)
#pragma unroll
                for (int j = 0; j < 4; j++) {
                    s[i][j] = fmaf(qv[i].x, kv[j].x, s[i][j]);
                    s[i][j] = fmaf(qv[i].y, kv[j].y, s[i][j]);
                    s[i][j] = fmaf(qv[i].z, kv[j].z, s[i][j]);
                    s[i][j] = fmaf(qv[i].w, kv[j].w, s[i][j]);
                }
        }

        // ---- mask (causal + segment) ----
#pragma unroll
        for (int i = 0; i < 4; i++) {
            const int r = m0 + ty * 4 + i;
#pragma unroll
            for (int j = 0; j < 4; j++) {
                const int c = n0 + tx * 4 + j;
                const bool ok = (c <= r) && (segKs[tx * 4 + j] == segq[i]);
                if (!ok) s[i][j] = -1e30f;
            }
        }

        // ---- online softmax update ----
        float alpha[4];
#pragma unroll
        for (int i = 0; i < 4; i++) {
            float mt = fmaxf(fmaxf(s[i][0], s[i][1]), fmaxf(s[i][2], s[i][3]));
#pragma unroll
            for (int off = 8; off > 0; off >>= 1)
                mt = fmaxf(mt, __shfl_xor_sync(0xffffffffu, mt, off, 16));
            const float mn = fmaxf(m_i[i], mt);
            alpha[i] = __expf(m_i[i] - mn);   // all-masked-so-far garbage flushed by alpha=0 later
            m_i[i] = mn;
            float lt = 0.f;
#pragma unroll
            for (int j = 0; j < 4; j++) {
                const float p = __expf(s[i][j] - mn);
                s[i][j] = p;
                lt += p;
            }
#pragma unroll
            for (int off = 8; off > 0; off >>= 1)
                lt += __shfl_xor_sync(0xffffffffu, lt, off, 16);
            l_i[i] = l_i[i] * alpha[i] + lt;
        }

        // ---- write P to smem ----
#pragma unroll
        for (int i = 0; i < 4; i++)
            *(float4*)(Ps + (ty * 4 + i) * PSTRIDE + tx * 4) =
                make_float4(s[i][0], s[i][1], s[i][2], s[i][3]);
        __syncthreads();

        // ---- rescale O, then O += P @ V : thread owns rows ty*4+i, cols 32j+2tx ----
#pragma unroll
        for (int i = 0; i < 4; i++)
#pragma unroll
            for (int j = 0; j < 8; j++) acc[i][j] *= alpha[i];

#pragma unroll 4
        for (int n = 0; n < BN; n++) {
            const float p0 = Ps[(ty * 4 + 0) * PSTRIDE + n];
            const float p1 = Ps[(ty * 4 + 1) * PSTRIDE + n];
            const float p2 = Ps[(ty * 4 + 2) * PSTRIDE + n];
            const float p3 = Ps[(ty * 4 + 3) * PSTRIDE + n];
#pragma unroll
            for (int j = 0; j < 4; j++) {
                const float2 vv = *(float2*)(Vs + n * KSTRIDE + j * 32 + tx * 2);
                acc[0][2*j]   = fmaf(p0, vv.x, acc[0][2*j]);
                acc[0][2*j+1] = fmaf(p0, vv.y, acc[0][2*j+1]);
                acc[1][2*j]   = fmaf(p1, vv.x, acc[1][2*j]);
                acc[1][2*j+1] = fmaf(p1, vv.y, acc[1][2*j+1]);
                acc[2][2*j]   = fmaf(p2, vv.x, acc[2][2*j]);
                acc[2][2*j+1] = fmaf(p2, vv.y, acc[2][2*j+1]);
                acc[3][2*j]   = fmaf(p3, vv.x, acc[3][2*j]);
                acc[3][2*j+1] = fmaf(p3, vv.y, acc[3][2*j+1]);
            }
        }
    }

    // ---- epilogue: O = acc / l ----
    float* obase = O + ((size_t)(b * T_LEN + m0) * NQ_H + qh) * D_DIM;
#pragma unroll
    for (int i = 0; i < 4; i++) {
        const float inv = 1.0f / l_i[i];    // diagonal always valid -> l > 0
#pragma unroll
        for (int j = 0; j < 4; j++) {
            float2 o2 = make_float2(acc[i][2*j] * inv, acc[i][2*j+1] * inv);
            *(float2*)(obase + (size_t)(ty * 4 + i) * NQ_H * D_DIM + j * 32 + tx * 2) = o2;
        }
    }
}

extern "C" void kernel_launch(void* const* d_in, const int* in_sizes, int n_in,
                              void* d_out, int out_size)
{
    const float* q   = (const float*)d_in[0];
    const float* k   = (const float*)d_in[1];
    const float* v   = (const float*)d_in[2];
    const int*   seg = (const int*)d_in[3];
    float*       out = (float*)d_out;

    const int B = in_sizes[0] / (T_LEN * NQ_H * D_DIM);

    const size_t smem = (size_t)(3 * BM * KSTRIDE + BM * PSTRIDE) * sizeof(float)
                      + (size_t)BN * sizeof(int);   // ~119 KB
    cudaFuncSetAttribute(attn_fwd, cudaFuncAttributeMaxDynamicSharedMemorySize, (int)smem);

    dim3 grid(T_LEN / BM, NQ_H, B);
    attn_fwd<<<grid, NTHREADS, smem>>>(q, k, v, seg, out);
}

// round 6
// speedup vs baseline: 3.2883x; 3.2883x over previous
#include <cuda_runtime.h>
#include <cuda_bf16.h>
#include <cstdint>

#define T_LEN    2048
#define D_DIM    128
#define NQ_H     32
#define NKV_H    8
#define BM       128
#define BN       64
#define NTHREADS 256
#define LOG2E    1.4426950408889634f

// smem: bf16 tiles, row stride 136 elems (272 B) -> conflict-free ldmatrix
#define SD       136
#define ROWB     272
#define OFF_QHI  0
#define OFF_QLO  34816
#define OFF_KHI  69632
#define OFF_KLO  87040
#define OFF_VHI  104448
#define OFF_VLO  121856
#define OFF_SEG  139264
#define SMEM_TOTAL 139520

__device__ __forceinline__ uint32_t smem_u32(const void* p) {
    uint32_t a;
    asm("{ .reg .u64 t; cvta.to.shared.u64 t, %1; cvt.u32.u64 %0, t; }" : "=r"(a) : "l"(p));
    return a;
}
__device__ __forceinline__ float ex2f(float x) {
    float r;
    asm("ex2.approx.ftz.f32 %0, %1;" : "=f"(r) : "f"(x));
    return r;
}
__device__ __forceinline__ void mma16816(float* d, const uint32_t* a, const uint32_t* b) {
    asm volatile("mma.sync.aligned.m16n8k16.row.col.f32.bf16.bf16.f32 "
                 "{%0,%1,%2,%3}, {%4,%5,%6,%7}, {%8,%9}, {%0,%1,%2,%3};"
                 : "+f"(d[0]), "+f"(d[1]), "+f"(d[2]), "+f"(d[3])
                 : "r"(a[0]), "r"(a[1]), "r"(a[2]), "r"(a[3]), "r"(b[0]), "r"(b[1]));
}
__device__ __forceinline__ void ldsm_x4(uint32_t* r, uint32_t addr) {
    asm volatile("ldmatrix.sync.aligned.m8n8.x4.shared.b16 {%0,%1,%2,%3}, [%4];"
                 : "=r"(r[0]), "=r"(r[1]), "=r"(r[2]), "=r"(r[3]) : "r"(addr));
}
__device__ __forceinline__ void ldsm_x2(uint32_t* r, uint32_t addr) {
    asm volatile("ldmatrix.sync.aligned.m8n8.x2.shared.b16 {%0,%1}, [%2];"
                 : "=r"(r[0]), "=r"(r[1]) : "r"(addr));
}
__device__ __forceinline__ void ldsm_x2t(uint32_t* r, uint32_t addr) {
    asm volatile("ldmatrix.sync.aligned.m8n8.x2.trans.shared.b16 {%0,%1}, [%2];"
                 : "=r"(r[0]), "=r"(r[1]) : "r"(addr));
}
// split x,y into packed bf16x2 hi and lo
__device__ __forceinline__ void split2(float x, float y, uint32_t& hi, uint32_t& lo) {
    __nv_bfloat162 h = __floats2bfloat162_rn(x, y);
    float hx = __low2float(h), hy = __high2float(h);
    __nv_bfloat162 l = __floats2bfloat162_rn(x - hx, y - hy);
    hi = *(uint32_t*)&h;
    lo = *(uint32_t*)&l;
}

__global__ __launch_bounds__(NTHREADS, 1)
void attn_fwd_mma(const float* __restrict__ Q, const float* __restrict__ K,
                  const float* __restrict__ V, const int* __restrict__ SEG,
                  float* __restrict__ O)
{
    extern __shared__ __align__(16) char smem[];
    const uint32_t sb = smem_u32(smem);

    const int b   = blockIdx.z;
    const int qh  = blockIdx.y;
    const int kvh = qh >> 2;
    const int m0  = ((int)gridDim.x - 1 - (int)blockIdx.x) * BM;  // heavy blocks first

    const int tid  = threadIdx.x;
    const int w    = tid >> 5;
    const int lane = tid & 31;
    const int g    = lane >> 2;       // quad group = row within fragment
    const int qc   = lane & 3;        // quad lane  = col pair
    const int l2   = lane & 15;

    const int* segB = SEG + b * T_LEN;
    int* segK = (int*)(smem + OFF_SEG);

    // ---- load Q tile [BM x D], scale by log2e, split hi/lo ----
    const float* qbase = Q + ((size_t)(b * T_LEN + m0) * NQ_H + qh) * D_DIM;
    for (int i = tid; i < BM * (D_DIM / 4); i += NTHREADS) {
        int r = i >> 5, e = (i & 31) * 4;
        float4 qv = *(const float4*)(qbase + (size_t)r * NQ_H * D_DIM + e);
        uint32_t h0, l0, h1, l1;
        split2(qv.x * LOG2E, qv.y * LOG2E, h0, l0);
        split2(qv.z * LOG2E, qv.w * LOG2E, h1, l1);
        uint32_t off = (uint32_t)(r * ROWB + e * 2);
        *(uint32_t*)(smem + OFF_QHI + off)     = h0;
        *(uint32_t*)(smem + OFF_QHI + off + 4) = h1;
        *(uint32_t*)(smem + OFF_QLO + off)     = l0;
        *(uint32_t*)(smem + OFF_QLO + off + 4) = l1;
    }

    // per-thread rows (two per thread, 8 apart)
    const int rG0 = m0 + w * 16 + g;
    const int rG1 = rG0 + 8;
    const int segRowMin = segB[m0];
    const int segRowMax = segB[m0 + BM - 1];
    int rowSeg0, rowSeg1;

    float m0r = -1e30f, m1r = -1e30f, l0r = 0.f, l1r = 0.f;
    float o[16][4];
#pragma unroll
    for (int j = 0; j < 16; j++)
#pragma unroll
        for (int u = 0; u < 4; u++) o[j][u] = 0.f;

    const float* kbase0 = K + ((size_t)b * T_LEN * NKV_H + kvh) * D_DIM;
    const float* vbase0 = V + ((size_t)b * T_LEN * NKV_H + kvh) * D_DIM;

    // ldmatrix base addresses (per-lane row mapping)
    const int arow = w * 16 + (lane & 7) + ((lane >> 3) & 1) * 8;
    const uint32_t aColOff = (uint32_t)(((lane >> 4) * 8) * 2);
    const uint32_t aHiBase = sb + OFF_QHI + (uint32_t)arow * ROWB + aColOff;
    const uint32_t aLoBase = sb + OFF_QLO + (uint32_t)arow * ROWB + aColOff;
    const uint32_t bRowOff = (uint32_t)((l2 & 7) * ROWB + (l2 >> 3) * 16);

    rowSeg0 = segB[rG0];
    rowSeg1 = segB[rG1];

    const int nTiles = m0 / BN + 2;
    for (int nt = 0; nt < nTiles; nt++) {
        const int n0 = nt * BN;
        if (segB[n0] > segRowMax || segB[n0 + BN - 1] < segRowMin) continue;

        // ---- refill K/V smem (hi/lo split) ----
        __syncthreads();   // all warps done reading previous tile
        for (int i = tid; i < BN * (D_DIM / 4); i += NTHREADS) {
            int n = i >> 5, e = (i & 31) * 4;
            float4 kv = *(const float4*)(kbase0 + (size_t)(n0 + n) * NKV_H * D_DIM + e);
            float4 vv = *(const float4*)(vbase0 + (size_t)(n0 + n) * NKV_H * D_DIM + e);
            uint32_t off = (uint32_t)(n * ROWB + e * 2);
            uint32_t h0, lo0, h1, lo1;
            split2(kv.x, kv.y, h0, lo0); split2(kv.z, kv.w, h1, lo1);
            *(uint32_t*)(smem + OFF_KHI + off)     = h0;
            *(uint32_t*)(smem + OFF_KHI + off + 4) = h1;
            *(uint32_t*)(smem + OFF_KLO + off)     = lo0;
            *(uint32_t*)(smem + OFF_KLO + off + 4) = lo1;
            split2(vv.x, vv.y, h0, lo0); split2(vv.z, vv.w, h1, lo1);
            *(uint32_t*)(smem + OFF_VHI + off)     = h0;
            *(uint32_t*)(smem + OFF_VHI + off + 4) = h1;
            *(uint32_t*)(smem + OFF_VLO + off)     = lo0;
            *(uint32_t*)(smem + OFF_VLO + off + 4) = lo1;
        }
        if (tid < BN) segK[tid] = segB[n0 + tid];
        __syncthreads();

        // ---- S = Q K^T (3-term) : warp owns 16 rows x 64 cols ----
        float s[8][4];
#pragma unroll
        for (int j = 0; j < 8; j++)
#pragma unroll
            for (int u = 0; u < 4; u++) s[j][u] = 0.f;

#pragma unroll
        for (int kc = 0; kc < 8; kc++) {
            uint32_t aHi[4], aLo[4];
            ldsm_x4(aHi, aHiBase + kc * 32);
            ldsm_x4(aLo, aLoBase + kc * 32);
#pragma unroll
            for (int j = 0; j < 8; j++) {
                uint32_t bHi[2], bLo[2];
                const uint32_t bo = (uint32_t)(j * 8 * ROWB) + bRowOff + kc * 32;
                ldsm_x2(bHi, sb + OFF_KHI + bo);
                ldsm_x2(bLo, sb + OFF_KLO + bo);
                mma16816(s[j], aHi, bHi);
                mma16816(s[j], aHi, bLo);
                mma16816(s[j], aLo, bHi);
            }
        }

        // ---- mask + online softmax (warp-local) ----
        float mt0 = -1e30f, mt1 = -1e30f;
#pragma unroll
        for (int j = 0; j < 8; j++) {
            const int col = 8 * j + 2 * qc;
            const int c0 = n0 + col, c1 = c0 + 1;
            const int sg0 = segK[col], sg1 = segK[col + 1];
            if (!(c0 <= rG0 && sg0 == rowSeg0)) s[j][0] = -1e30f;
            if (!(c1 <= rG0 && sg1 == rowSeg0)) s[j][1] = -1e30f;
            if (!(c0 <= rG1 && sg0 == rowSeg1)) s[j][2] = -1e30f;
            if (!(c1 <= rG1 && sg1 == rowSeg1)) s[j][3] = -1e30f;
            mt0 = fmaxf(mt0, fmaxf(s[j][0], s[j][1]));
            mt1 = fmaxf(mt1, fmaxf(s[j][2], s[j][3]));
        }
        mt0 = fmaxf(mt0, __shfl_xor_sync(0xffffffffu, mt0, 1));
        mt0 = fmaxf(mt0, __shfl_xor_sync(0xffffffffu, mt0, 2));
        mt1 = fmaxf(mt1, __shfl_xor_sync(0xffffffffu, mt1, 1));
        mt1 = fmaxf(mt1, __shfl_xor_sync(0xffffffffu, mt1, 2));

        const float mn0 = fmaxf(m0r, mt0), mn1 = fmaxf(m1r, mt1);
        const float al0 = ex2f(m0r - mn0), al1 = ex2f(m1r - mn1);
        m0r = mn0; m1r = mn1;

        float ls0 = 0.f, ls1 = 0.f;
#pragma unroll
        for (int j = 0; j < 8; j++) {
            s[j][0] = ex2f(s[j][0] - mn0);
            s[j][1] = ex2f(s[j][1] - mn0);
            s[j][2] = ex2f(s[j][2] - mn1);
            s[j][3] = ex2f(s[j][3] - mn1);
            ls0 += s[j][0] + s[j][1];
            ls1 += s[j][2] + s[j][3];
        }
        ls0 += __shfl_xor_sync(0xffffffffu, ls0, 1);
        ls0 += __shfl_xor_sync(0xffffffffu, ls0, 2);
        ls1 += __shfl_xor_sync(0xffffffffu, ls1, 1);
        ls1 += __shfl_xor_sync(0xffffffffu, ls1, 2);
        l0r = l0r * al0 + ls0;
        l1r = l1r * al1 + ls1;

        // ---- rescale O ----
#pragma unroll
        for (int j = 0; j < 16; j++) {
            o[j][0] *= al0; o[j][1] *= al0;
            o[j][2] *= al1; o[j][3] *= al1;
        }

        // ---- O += P V  (P in registers as A-fragments; V via trans ldmatrix) ----
#pragma unroll
        for (int kc2 = 0; kc2 < 4; kc2++) {
            uint32_t pHi[4], pLo[4];
            split2(s[2*kc2][0],   s[2*kc2][1],   pHi[0], pLo[0]);
            split2(s[2*kc2][2],   s[2*kc2][3],   pHi[1], pLo[1]);
            split2(s[2*kc2+1][0], s[2*kc2+1][1], pHi[2], pLo[2]);
            split2(s[2*kc2+1][2], s[2*kc2+1][3], pHi[3], pLo[3]);
            const uint32_t vRowOff =
                (uint32_t)((kc2 * 16 + (l2 & 7) + (l2 >> 3) * 8) * ROWB);
#pragma unroll
            for (int j2 = 0; j2 < 16; j2++) {
                uint32_t bHi[2], bLo[2];
                ldsm_x2t(bHi, sb + OFF_VHI + vRowOff + j2 * 16);
                ldsm_x2t(bLo, sb + OFF_VLO + vRowOff + j2 * 16);
                mma16816(o[j2], pHi, bHi);
                mma16816(o[j2], pHi, bLo);
                mma16816(o[j2], pLo, bHi);
            }
        }
    }

    // ---- epilogue ----
    {
        const float i0 = 1.0f / l0r, i1 = 1.0f / l1r;
        float* ob0 = O + ((size_t)(b * T_LEN + rG0) * NQ_H + qh) * D_DIM;
        float* ob1 = O + ((size_t)(b * T_LEN + rG1) * NQ_H + qh) * D_DIM;
#pragma unroll
        for (int j2 = 0; j2 < 16; j2++) {
            const int col = 8 * j2 + 2 * qc;
            *(float2*)(ob0 + col) = make_float2(o[j2][0] * i0, o[j2][1] * i0);
            *(float2*)(ob1 + col) = make_float2(o[j2][2] * i1, o[j2][3] * i1);
        }
    }
}

extern "C" void kernel_launch(void* const* d_in, const int* in_sizes, int n_in,
                              void* d_out, int out_size)
{
    const float* q   = (const float*)d_in[0];
    const float* k   = (const float*)d_in[1];
    const float* v   = (const float*)d_in[2];
    const int*   seg = (const int*)d_in[3];
    float*       out = (float*)d_out;

    const int B = in_sizes[0] / (T_LEN * NQ_H * D_DIM);

    cudaFuncSetAttribute(attn_fwd_mma, cudaFuncAttributeMaxDynamicSharedMemorySize, SMEM_TOTAL);
    dim3 grid(T_LEN / BM, NQ_H, B);
    attn_fwd_mma<<<grid, NTHREADS, SMEM_TOTAL>>>(q, k, v, seg, out);
}

// round 7
// speedup vs baseline: 3.5736x; 1.0868x over previous
#include <cuda_runtime.h>
#include <cuda_bf16.h>
#include <cstdint>

#define T_LEN    2048
#define D_DIM    128
#define NQ_H     32
#define NKV_H    8
#define B_MAX    2
#define BM       128
#define BN       64
#define NTHREADS 256
#define LOG2E    1.4426950408889634f

// smem (bytes): bf16 tiles, row stride 272B -> conflict-free ldmatrix
#define ROWB     272
#define OFF_QHI  0
#define OFF_QLO  34816
#define OFF_KV   69632      // 2 buffers x (KHI,KLO,VHI,VLO) x 17408
#define SUBSZ    17408
#define BUFSZ    69632
#define OFF_SEG  208896     // 2 x 256
#define SMEM_TOTAL 209408

// pre-split K/V scratch (bf16 hi/lo), layout [b][kvh][t][d]
#define KV_ELEMS (B_MAX * NKV_H * T_LEN * D_DIM)
__device__ __nv_bfloat16 g_khi[KV_ELEMS];
__device__ __nv_bfloat16 g_klo[KV_ELEMS];
__device__ __nv_bfloat16 g_vhi[KV_ELEMS];
__device__ __nv_bfloat16 g_vlo[KV_ELEMS];

__device__ __forceinline__ uint32_t smem_u32(const void* p) {
    uint32_t a;
    asm("{ .reg .u64 t; cvta.to.shared.u64 t, %1; cvt.u32.u64 %0, t; }" : "=r"(a) : "l"(p));
    return a;
}
__device__ __forceinline__ float ex2f(float x) {
    float r;
    asm("ex2.approx.ftz.f32 %0, %1;" : "=f"(r) : "f"(x));
    return r;
}
__device__ __forceinline__ void mma16816(float* d, const uint32_t* a, const uint32_t* b) {
    asm volatile("mma.sync.aligned.m16n8k16.row.col.f32.bf16.bf16.f32 "
                 "{%0,%1,%2,%3}, {%4,%5,%6,%7}, {%8,%9}, {%0,%1,%2,%3};"
                 : "+f"(d[0]), "+f"(d[1]), "+f"(d[2]), "+f"(d[3])
                 : "r"(a[0]), "r"(a[1]), "r"(a[2]), "r"(a[3]), "r"(b[0]), "r"(b[1]));
}
__device__ __forceinline__ void ldsm_x4(uint32_t* r, uint32_t addr) {
    asm volatile("ldmatrix.sync.aligned.m8n8.x4.shared.b16 {%0,%1,%2,%3}, [%4];"
                 : "=r"(r[0]), "=r"(r[1]), "=r"(r[2]), "=r"(r[3]) : "r"(addr));
}
__device__ __forceinline__ void ldsm_x4t(uint32_t* r, uint32_t addr) {
    asm volatile("ldmatrix.sync.aligned.m8n8.x4.trans.shared.b16 {%0,%1,%2,%3}, [%4];"
                 : "=r"(r[0]), "=r"(r[1]), "=r"(r[2]), "=r"(r[3]) : "r"(addr));
}
__device__ __forceinline__ void split2(float x, float y, uint32_t& hi, uint32_t& lo) {
    __nv_bfloat162 h = __floats2bfloat162_rn(x, y);
    float hx = __low2float(h), hy = __high2float(h);
    __nv_bfloat162 l = __floats2bfloat162_rn(x - hx, y - hy);
    hi = *(uint32_t*)&h;
    lo = *(uint32_t*)&l;
}
__device__ __forceinline__ void cp16(uint32_t dst, const void* src) {
    size_t g = __cvta_generic_to_global(src);
    asm volatile("cp.async.cg.shared.global [%0], [%1], 16;" :: "r"(dst), "l"(g) : "memory");
}
#define CP_COMMIT() asm volatile("cp.async.commit_group;" ::: "memory")
#define CP_WAIT0()  asm volatile("cp.async.wait_group 0;" ::: "memory")

// ---- prep kernel: split K/V f32 -> bf16 hi/lo, relayout [b][kvh][t][d] ----
__global__ void prep_kv(const float* __restrict__ K, const float* __restrict__ V) {
    const int t = blockIdx.x, h = blockIdx.y, b = blockIdx.z;
    const int d = threadIdx.x * 2;
    const size_t src = ((size_t)(b * T_LEN + t) * NKV_H + h) * D_DIM + d;
    const size_t dst = ((size_t)(b * NKV_H + h) * T_LEN + t) * D_DIM + d;
    float2 kv = *(const float2*)(K + src);
    float2 vv = *(const float2*)(V + src);
    uint32_t hh, ll;
    split2(kv.x, kv.y, hh, ll);
    *(uint32_t*)(g_khi + dst) = hh; *(uint32_t*)(g_klo + dst) = ll;
    split2(vv.x, vv.y, hh, ll);
    *(uint32_t*)(g_vhi + dst) = hh; *(uint32_t*)(g_vlo + dst) = ll;
}

__device__ __forceinline__ void prefetch_tile(uint32_t sb, int buf, int tid,
                                              size_t kvoff, int n0,
                                              const int* __restrict__ segB) {
    const uint32_t bufBase = sb + OFF_KV + buf * BUFSZ;
    const __nv_bfloat16* srcs[4] = { g_khi + kvoff, g_klo + kvoff,
                                     g_vhi + kvoff, g_vlo + kvoff };
#pragma unroll
    for (int sub = 0; sub < 4; sub++) {
        const __nv_bfloat16* sp = srcs[sub] + (size_t)n0 * D_DIM;
#pragma unroll
        for (int q = 0; q < 4; q++) {
            const int i = tid + q * NTHREADS;
            const int row = i >> 4, ch = i & 15;
            cp16(bufBase + sub * SUBSZ + row * ROWB + ch * 16,
                 sp + row * D_DIM + ch * 8);
        }
    }
    if (tid < 16) cp16(sb + OFF_SEG + buf * 256 + tid * 16, segB + n0 + tid * 4);
}

__global__ __launch_bounds__(NTHREADS, 1)
void attn_fwd_mma(const float* __restrict__ Q, const int* __restrict__ SEG,
                  float* __restrict__ O)
{
    extern __shared__ __align__(16) char smem[];
    const uint32_t sb = smem_u32(smem);

    const int b   = blockIdx.z;
    const int qh  = blockIdx.y;
    const int kvh = qh >> 2;
    const int m0  = ((int)gridDim.x - 1 - (int)blockIdx.x) * BM;  // heavy blocks first

    const int tid  = threadIdx.x;
    const int w    = tid >> 5;
    const int lane = tid & 31;
    const int g    = lane >> 2;
    const int qc   = lane & 3;

    const int* segB = SEG + b * T_LEN;
    const size_t kvoff = ((size_t)b * NKV_H + kvh) * T_LEN * D_DIM;

    // ---- load Q tile [BM x D], scale by log2e, split hi/lo ----
    const float* qbase = Q + ((size_t)(b * T_LEN + m0) * NQ_H + qh) * D_DIM;
    for (int i = tid; i < BM * (D_DIM / 4); i += NTHREADS) {
        int r = i >> 5, e = (i & 31) * 4;
        float4 qv = *(const float4*)(qbase + (size_t)r * NQ_H * D_DIM + e);
        uint32_t h0, l0, h1, l1;
        split2(qv.x * LOG2E, qv.y * LOG2E, h0, l0);
        split2(qv.z * LOG2E, qv.w * LOG2E, h1, l1);
        uint32_t off = (uint32_t)(r * ROWB + e * 2);
        *(uint32_t*)(smem + OFF_QHI + off)     = h0;
        *(uint32_t*)(smem + OFF_QHI + off + 4) = h1;
        *(uint32_t*)(smem + OFF_QLO + off)     = l0;
        *(uint32_t*)(smem + OFF_QLO + off + 4) = l1;
    }

    const int rG0 = m0 + w * 16 + g;
    const int rG1 = rG0 + 8;
    const int segRowMin = segB[m0];
    const int segRowMax = segB[m0 + BM - 1];
    const int rowSeg0 = segB[rG0];
    const int rowSeg1 = segB[rG1];

    float m0r = -1e30f, m1r = -1e30f, l0r = 0.f, l1r = 0.f;
    float o[16][4];
#pragma unroll
    for (int j = 0; j < 16; j++)
#pragma unroll
        for (int u = 0; u < 4; u++) o[j][u] = 0.f;

    // ldmatrix lane address components
    const int arow = w * 16 + (lane & 7) + ((lane >> 3) & 1) * 8;
    const uint32_t aColOff = (uint32_t)(((lane >> 4) * 8) * 2);
    const uint32_t aHiBase = sb + OFF_QHI + (uint32_t)arow * ROWB + aColOff;
    const uint32_t aLoBase = sb + OFF_QLO + (uint32_t)arow * ROWB + aColOff;
    // K x4: matrices (j b0, j b1, j+1 b0, j+1 b1)
    const uint32_t bRow4 = (uint32_t)(((lane & 7) + ((lane >> 4) & 1) * 8) * ROWB
                                      + ((lane >> 3) & 1) * 16);
    // V trans x4: matrices (j2 b0, j2 b1, j2+1 b0, j2+1 b1)
    const uint32_t vRow4 = (uint32_t)(((lane & 7) + ((lane >> 3) & 1) * 8) * ROWB
                                      + ((lane >> 4) & 1) * 16);

    const int nTiles = m0 / BN + 2;

    // ---- find first valid tile, start prefetch ----
    int ntCur = -1;
    for (int t = 0; t < nTiles; t++) {
        if (!(segB[t * BN] > segRowMax || segB[t * BN + BN - 1] < segRowMin)) { ntCur = t; break; }
    }
    int buf = 0;
    prefetch_tile(sb, buf, tid, kvoff, ntCur * BN, segB);
    CP_COMMIT();

    while (ntCur >= 0) {
        // lookahead: next valid tile
        int ntNext = -1;
        for (int t = ntCur + 1; t < nTiles; t++) {
            if (!(segB[t * BN] > segRowMax || segB[t * BN + BN - 1] < segRowMin)) { ntNext = t; break; }
        }

        CP_WAIT0();
        __syncthreads();   // tile data visible; all warps done with buf^1

        if (ntNext >= 0) { prefetch_tile(sb, buf ^ 1, tid, kvoff, ntNext * BN, segB); CP_COMMIT(); }

        const int n0 = ntCur * BN;
        const uint32_t bufBase = sb + OFF_KV + buf * BUFSZ;
        const int* segK = (const int*)(smem + OFF_SEG + buf * 256);

        // ---- S = Q K^T (3-term) ----
        float s[8][4];
#pragma unroll
        for (int j = 0; j < 8; j++)
#pragma unroll
            for (int u = 0; u < 4; u++) s[j][u] = 0.f;

#pragma unroll
        for (int kc = 0; kc < 8; kc++) {
            uint32_t aHi[4], aLo[4];
            ldsm_x4(aHi, aHiBase + kc * 32);
            ldsm_x4(aLo, aLoBase + kc * 32);
#pragma unroll
            for (int jp = 0; jp < 4; jp++) {
                uint32_t bHi[4], bLo[4];
                const uint32_t bo = bufBase + (uint32_t)(jp * 16 * ROWB) + bRow4 + kc * 32;
                ldsm_x4(bHi, bo);
                ldsm_x4(bLo, bo + SUBSZ);
                mma16816(s[2*jp],   aHi, bHi);
                mma16816(s[2*jp],   aHi, bLo);
                mma16816(s[2*jp],   aLo, bHi);
                mma16816(s[2*jp+1], aHi, bHi + 2);
                mma16816(s[2*jp+1], aHi, bLo + 2);
                mma16816(s[2*jp+1], aLo, bHi + 2);
            }
        }

        // ---- mask + online softmax (warp-local) ----
        float mt0 = -1e30f, mt1 = -1e30f;
#pragma unroll
        for (int j = 0; j < 8; j++) {
            const int col = 8 * j + 2 * qc;
            const int c0 = n0 + col, c1 = c0 + 1;
            const int sg0 = segK[col], sg1 = segK[col + 1];
            if (!(c0 <= rG0 && sg0 == rowSeg0)) s[j][0] = -1e30f;
            if (!(c1 <= rG0 && sg1 == rowSeg0)) s[j][1] = -1e30f;
            if (!(c0 <= rG1 && sg0 == rowSeg1)) s[j][2] = -1e30f;
            if (!(c1 <= rG1 && sg1 == rowSeg1)) s[j][3] = -1e30f;
            mt0 = fmaxf(mt0, fmaxf(s[j][0], s[j][1]));
            mt1 = fmaxf(mt1, fmaxf(s[j][2], s[j][3]));
        }
        mt0 = fmaxf(mt0, __shfl_xor_sync(0xffffffffu, mt0, 1));
        mt0 = fmaxf(mt0, __shfl_xor_sync(0xffffffffu, mt0, 2));
        mt1 = fmaxf(mt1, __shfl_xor_sync(0xffffffffu, mt1, 1));
        mt1 = fmaxf(mt1, __shfl_xor_sync(0xffffffffu, mt1, 2));

        const float mn0 = fmaxf(m0r, mt0), mn1 = fmaxf(m1r, mt1);
        const float al0 = ex2f(m0r - mn0), al1 = ex2f(m1r - mn1);
        m0r = mn0; m1r = mn1;

        float ls0 = 0.f, ls1 = 0.f;
#pragma unroll
        for (int j = 0; j < 8; j++) {
            s[j][0] = ex2f(s[j][0] - mn0);
            s[j][1] = ex2f(s[j][1] - mn0);
            s[j][2] = ex2f(s[j][2] - mn1);
            s[j][3] = ex2f(s[j][3] - mn1);
            ls0 += s[j][0] + s[j][1];
            ls1 += s[j][2] + s[j][3];
        }
        ls0 += __shfl_xor_sync(0xffffffffu, ls0, 1);
        ls0 += __shfl_xor_sync(0xffffffffu, ls0, 2);
        ls1 += __shfl_xor_sync(0xffffffffu, ls1, 1);
        ls1 += __shfl_xor_sync(0xffffffffu, ls1, 2);
        l0r = l0r * al0 + ls0;
        l1r = l1r * al1 + ls1;

#pragma unroll
        for (int j = 0; j < 16; j++) {
            o[j][0] *= al0; o[j][1] *= al0;
            o[j][2] *= al1; o[j][3] *= al1;
        }

        // ---- O += P V ----
        const uint32_t vBase = bufBase + 2 * SUBSZ;
#pragma unroll
        for (int kc2 = 0; kc2 < 4; kc2++) {
            uint32_t pHi[4], pLo[4];
            split2(s[2*kc2][0],   s[2*kc2][1],   pHi[0], pLo[0]);
            split2(s[2*kc2][2],   s[2*kc2][3],   pHi[1], pLo[1]);
            split2(s[2*kc2+1][0], s[2*kc2+1][1], pHi[2], pLo[2]);
            split2(s[2*kc2+1][2], s[2*kc2+1][3], pHi[3], pLo[3]);
            const uint32_t vRowBase = vBase + (uint32_t)(kc2 * 16 * ROWB) + vRow4;
#pragma unroll
            for (int j2p = 0; j2p < 8; j2p++) {
                uint32_t vHi[4], vLo[4];
                const uint32_t bo = vRowBase + j2p * 32;
                ldsm_x4t(vHi, bo);
                ldsm_x4t(vLo, bo + SUBSZ);
                mma16816(o[2*j2p],   pHi, vHi);
                mma16816(o[2*j2p],   pHi, vLo);
                mma16816(o[2*j2p],   pLo, vHi);
                mma16816(o[2*j2p+1], pHi, vHi + 2);
                mma16816(o[2*j2p+1], pHi, vLo + 2);
                mma16816(o[2*j2p+1], pLo, vHi + 2);
            }
        }

        buf ^= 1;
        ntCur = ntNext;
    }

    // ---- epilogue ----
    {
        const float i0 = 1.0f / l0r, i1 = 1.0f / l1r;
        float* ob0 = O + ((size_t)(b * T_LEN + rG0) * NQ_H + qh) * D_DIM;
        float* ob1 = O + ((size_t)(b * T_LEN + rG1) * NQ_H + qh) * D_DIM;
#pragma unroll
        for (int j2 = 0; j2 < 16; j2++) {
            const int col = 8 * j2 + 2 * qc;
            *(float2*)(ob0 + col) = make_float2(o[j2][0] * i0, o[j2][1] * i0);
            *(float2*)(ob1 + col) = make_float2(o[j2][2] * i1, o[j2][3] * i1);
        }
    }
}

extern "C" void kernel_launch(void* const* d_in, const int* in_sizes, int n_in,
                              void* d_out, int out_size)
{
    const float* q   = (const float*)d_in[0];
    const float* k   = (const float*)d_in[1];
    const float* v   = (const float*)d_in[2];
    const int*   seg = (const int*)d_in[3];
    float*       out = (float*)d_out;

    const int B = in_sizes[0] / (T_LEN * NQ_H * D_DIM);

    dim3 pgrid(T_LEN, NKV_H, B);
    prep_kv<<<pgrid, 64>>>(k, v);

    cudaFuncSetAttribute(attn_fwd_mma, cudaFuncAttributeMaxDynamicSharedMemorySize, SMEM_TOTAL);
    dim3 grid(T_LEN / BM, NQ_H, B);
    attn_fwd_mma<<<grid, NTHREADS, SMEM_TOTAL>>>(q, seg, out);
}

// round 9
// speedup vs baseline: 4.0854x; 1.1432x over previous
#include <cuda_runtime.h>
#include <cuda_bf16.h>
#include <cstdint>

#define T_LEN    2048
#define D_DIM    128
#define NQ_H     32
#define NKV_H    8
#define B_MAX    2
#define BM       64
#define BN       64
#define NTHREADS 128
#define LOG2E    1.4426950408889634f

// smem (bytes): bf16 tiles, row stride 272B -> conflict-free ldmatrix
#define ROWB     272
#define SUBSZ    17408
#define OFF_QHI  0
#define OFF_QLO  17408
#define OFF_KV   34816          // KHI,KLO,VHI,VLO x 17408
#define OFF_SEG  104448         // 64 ints
#define SMEM_TOTAL 104704

// pre-split K/V scratch (bf16 hi/lo), layout [b][kvh][t][d]
#define KV_ELEMS (B_MAX * NKV_H * T_LEN * D_DIM)
__device__ __nv_bfloat16 g_khi[KV_ELEMS];
__device__ __nv_bfloat16 g_klo[KV_ELEMS];
__device__ __nv_bfloat16 g_vhi[KV_ELEMS];
__device__ __nv_bfloat16 g_vlo[KV_ELEMS];

__device__ __forceinline__ uint32_t smem_u32(const void* p) {
    uint32_t a;
    asm("{ .reg .u64 t; cvta.to.shared.u64 t, %1; cvt.u32.u64 %0, t; }" : "=r"(a) : "l"(p));
    return a;
}
__device__ __forceinline__ float ex2f(float x) {
    float r;
    asm("ex2.approx.ftz.f32 %0, %1;" : "=f"(r) : "f"(x));
    return r;
}
__device__ __forceinline__ void mma16816(float* d, const uint32_t* a, const uint32_t* b) {
    asm volatile("mma.sync.aligned.m16n8k16.row.col.f32.bf16.bf16.f32 "
                 "{%0,%1,%2,%3}, {%4,%5,%6,%7}, {%8,%9}, {%0,%1,%2,%3};"
                 : "+f"(d[0]), "+f"(d[1]), "+f"(d[2]), "+f"(d[3])
                 : "r"(a[0]), "r"(a[1]), "r"(a[2]), "r"(a[3]), "r"(b[0]), "r"(b[1]));
}
__device__ __forceinline__ void ldsm_x4(uint32_t* r, uint32_t addr) {
    asm volatile("ldmatrix.sync.aligned.m8n8.x4.shared.b16 {%0,%1,%2,%3}, [%4];"
                 : "=r"(r[0]), "=r"(r[1]), "=r"(r[2]), "=r"(r[3]) : "r"(addr));
}
__device__ __forceinline__ void ldsm_x4t(uint32_t* r, uint32_t addr) {
    asm volatile("ldmatrix.sync.aligned.m8n8.x4.trans.shared.b16 {%0,%1,%2,%3}, [%4];"
                 : "=r"(r[0]), "=r"(r[1]), "=r"(r[2]), "=r"(r[3]) : "r"(addr));
}
__device__ __forceinline__ void split2(float x, float y, uint32_t& hi, uint32_t& lo) {
    __nv_bfloat162 h = __floats2bfloat162_rn(x, y);
    float hx = __low2float(h), hy = __high2float(h);
    __nv_bfloat162 l = __floats2bfloat162_rn(x - hx, y - hy);
    hi = *(uint32_t*)&h;
    lo = *(uint32_t*)&l;
}
__device__ __forceinline__ void cp16(uint32_t dst, const void* src) {
    size_t g = __cvta_generic_to_global(src);
    asm volatile("cp.async.cg.shared.global [%0], [%1], 16;" :: "r"(dst), "l"(g) : "memory");
}
#define CP_COMMIT() asm volatile("cp.async.commit_group;" ::: "memory")
#define CP_WAIT0()  asm volatile("cp.async.wait_group 0;" ::: "memory")

// ---- prep kernel: split K/V f32 -> bf16 hi/lo, relayout [b][kvh][t][d] ----
__global__ void prep_kv(const float* __restrict__ K, const float* __restrict__ V) {
    const int t = blockIdx.x, h = blockIdx.y, b = blockIdx.z;
    const int d = threadIdx.x * 2;
    const size_t src = ((size_t)(b * T_LEN + t) * NKV_H + h) * D_DIM + d;
    const size_t dst = ((size_t)(b * NKV_H + h) * T_LEN + t) * D_DIM + d;
    float2 kv = *(const float2*)(K + src);
    float2 vv = *(const float2*)(V + src);
    uint32_t hh, ll;
    split2(kv.x, kv.y, hh, ll);
    *(uint32_t*)(g_khi + dst) = hh; *(uint32_t*)(g_klo + dst) = ll;
    split2(vv.x, vv.y, hh, ll);
    *(uint32_t*)(g_vhi + dst) = hh; *(uint32_t*)(g_vlo + dst) = ll;
}

__device__ __forceinline__ void prefetch_tile(uint32_t sb, int tid, size_t kvoff, int n0,
                                              const int* __restrict__ segB) {
    const uint32_t base = sb + OFF_KV;
    const __nv_bfloat16* srcs[4] = { g_khi + kvoff, g_klo + kvoff,
                                     g_vhi + kvoff, g_vlo + kvoff };
#pragma unroll
    for (int sub = 0; sub < 4; sub++) {
        const __nv_bfloat16* sp = srcs[sub] + (size_t)n0 * D_DIM;
#pragma unroll
        for (int q = 0; q < 8; q++) {
            const int i = tid + q * NTHREADS;
            const int row = i >> 4, ch = i & 15;
            cp16(base + sub * SUBSZ + row * ROWB + ch * 16,
                 sp + row * D_DIM + ch * 8);
        }
    }
    if (tid < 16) cp16(sb + OFF_SEG + tid * 16, segB + n0 + tid * 4);
}

__global__ __launch_bounds__(NTHREADS, 2)
void attn_fwd_mma(const float* __restrict__ Q, const int* __restrict__ SEG,
                  float* __restrict__ O)
{
    extern __shared__ __align__(16) char smem[];
    const uint32_t sb = smem_u32(smem);

    const int b   = blockIdx.z;
    const int qh  = blockIdx.y;
    const int kvh = qh >> 2;
    const int m0  = ((int)gridDim.x - 1 - (int)blockIdx.x) * BM;  // heavy blocks first

    const int tid  = threadIdx.x;
    const int w    = tid >> 5;        // 0..3
    const int lane = tid & 31;
    const int g    = lane >> 2;
    const int qc   = lane & 3;

    const int* segB = SEG + b * T_LEN;
    const size_t kvoff = ((size_t)b * NKV_H + kvh) * T_LEN * D_DIM;

    // ---- load Q tile [BM x D], scale by log2e, split hi/lo ----
    const float* qbase = Q + ((size_t)(b * T_LEN + m0) * NQ_H + qh) * D_DIM;
    for (int i = tid; i < BM * (D_DIM / 4); i += NTHREADS) {
        int r = i >> 5, e = (i & 31) * 4;
        float4 qv = *(const float4*)(qbase + (size_t)r * NQ_H * D_DIM + e);
        uint32_t h0, l0, h1, l1;
        split2(qv.x * LOG2E, qv.y * LOG2E, h0, l0);
        split2(qv.z * LOG2E, qv.w * LOG2E, h1, l1);
        uint32_t off = (uint32_t)(r * ROWB + e * 2);
        *(uint32_t*)(smem + OFF_QHI + off)     = h0;
        *(uint32_t*)(smem + OFF_QHI + off + 4) = h1;
        *(uint32_t*)(smem + OFF_QLO + off)     = l0;
        *(uint32_t*)(smem + OFF_QLO + off + 4) = l1;
    }

    const int rG0 = m0 + w * 16 + g;
    const int rG1 = rG0 + 8;
    const int segRowMin = segB[m0];
    const int segRowMax = segB[m0 + BM - 1];
    const int rowSeg0 = segB[rG0];
    const int rowSeg1 = segB[rG1];

    float m0r = -1e30f, m1r = -1e30f, l0r = 0.f, l1r = 0.f;
    float o[16][4];
#pragma unroll
    for (int j = 0; j < 16; j++)
#pragma unroll
        for (int u = 0; u < 4; u++) o[j][u] = 0.f;

    // ldmatrix lane address components
    const int arow = w * 16 + (lane & 7) + ((lane >> 3) & 1) * 8;
    const uint32_t aColOff = (uint32_t)(((lane >> 4) * 8) * 2);
    const uint32_t aHiBase = sb + OFF_QHI + (uint32_t)arow * ROWB + aColOff;
    const uint32_t aLoBase = sb + OFF_QLO + (uint32_t)arow * ROWB + aColOff;
    const uint32_t bRow4 = (uint32_t)(((lane & 7) + ((lane >> 4) & 1) * 8) * ROWB
                                      + ((lane >> 3) & 1) * 16);
    const uint32_t vRow4 = (uint32_t)(((lane & 7) + ((lane >> 3) & 1) * 8) * ROWB
                                      + ((lane >> 4) & 1) * 16);

    const int nTiles = m0 / BN + 1;   // BM == BN == 64

    for (int nt = 0; nt < nTiles; nt++) {
        const int n0 = nt * BN;
        if (segB[n0] > segRowMax || segB[n0 + BN - 1] < segRowMin) continue;

        __syncthreads();   // all warps done reading previous tile
        prefetch_tile(sb, tid, kvoff, n0, segB);
        CP_COMMIT();
        CP_WAIT0();
        __syncthreads();   // tile visible to all warps

        const uint32_t bufBase = sb + OFF_KV;
        const int* segK = (const int*)(smem + OFF_SEG);

        // ---- S = Q K^T (3-term) ----
        float s[8][4];
#pragma unroll
        for (int j = 0; j < 8; j++)
#pragma unroll
            for (int u = 0; u < 4; u++) s[j][u] = 0.f;

#pragma unroll
        for (int kc = 0; kc < 8; kc++) {
            uint32_t aHi[4], aLo[4];
            ldsm_x4(aHi, aHiBase + kc * 32);
            ldsm_x4(aLo, aLoBase + kc * 32);
#pragma unroll
            for (int jp = 0; jp < 4; jp++) {
                uint32_t bHi[4], bLo[4];
                const uint32_t bo = bufBase + (uint32_t)(jp * 16 * ROWB) + bRow4 + kc * 32;
                ldsm_x4(bHi, bo);
                ldsm_x4(bLo, bo + SUBSZ);
                mma16816(s[2*jp],   aHi, bHi);
                mma16816(s[2*jp],   aHi, bLo);
                mma16816(s[2*jp],   aLo, bHi);
                mma16816(s[2*jp+1], aHi, bHi + 2);
                mma16816(s[2*jp+1], aHi, bLo + 2);
                mma16816(s[2*jp+1], aLo, bHi + 2);
            }
        }

        // ---- mask + online softmax (warp-local) ----
        float mt0 = -1e30f, mt1 = -1e30f;
#pragma unroll
        for (int j = 0; j < 8; j++) {
            const int col = 8 * j + 2 * qc;
            const int c0 = n0 + col, c1 = c0 + 1;
            const int sg0 = segK[col], sg1 = segK[col + 1];
            if (!(c0 <= rG0 && sg0 == rowSeg0)) s[j][0] = -1e30f;
            if (!(c1 <= rG0 && sg1 == rowSeg0)) s[j][1] = -1e30f;
            if (!(c0 <= rG1 && sg0 == rowSeg1)) s[j][2] = -1e30f;
            if (!(c1 <= rG1 && sg1 == rowSeg1)) s[j][3] = -1e30f;
            mt0 = fmaxf(mt0, fmaxf(s[j][0], s[j][1]));
            mt1 = fmaxf(mt1, fmaxf(s[j][2], s[j][3]));
        }
        mt0 = fmaxf(mt0, __shfl_xor_sync(0xffffffffu, mt0, 1));
        mt0 = fmaxf(mt0, __shfl_xor_sync(0xffffffffu, mt0, 2));
        mt1 = fmaxf(mt1, __shfl_xor_sync(0xffffffffu, mt1, 1));
        mt1 = fmaxf(mt1, __shfl_xor_sync(0xffffffffu, mt1, 2));

        const float mn0 = fmaxf(m0r, mt0), mn1 = fmaxf(m1r, mt1);
        const float al0 = ex2f(m0r - mn0), al1 = ex2f(m1r - mn1);
        m0r = mn0; m1r = mn1;

        float ls0 = 0.f, ls1 = 0.f;
#pragma unroll
        for (int j = 0; j < 8; j++) {
            s[j][0] = ex2f(s[j][0] - mn0);
            s[j][1] = ex2f(s[j][1] - mn0);
            s[j][2] = ex2f(s[j][2] - mn1);
            s[j][3] = ex2f(s[j][3] - mn1);
            ls0 += s[j][0] + s[j][1];
            ls1 += s[j][2] + s[j][3];
        }
        ls0 += __shfl_xor_sync(0xffffffffu, ls0, 1);
        ls0 += __shfl_xor_sync(0xffffffffu, ls0, 2);
        ls1 += __shfl_xor_sync(0xffffffffu, ls1, 1);
        ls1 += __shfl_xor_sync(0xffffffffu, ls1, 2);
        l0r = l0r * al0 + ls0;
        l1r = l1r * al1 + ls1;

        // ---- rescale O (skip if alpha==1 warp-wide) ----
        if (!__all_sync(0xffffffffu, (al0 == 1.f) && (al1 == 1.f))) {
#pragma unroll
            for (int j = 0; j < 16; j++) {
                o[j][0] *= al0; o[j][1] *= al0;
                o[j][2] *= al1; o[j][3] *= al1;
            }
        }

        // ---- O += P V ----
        const uint32_t vBase = bufBase + 2 * SUBSZ;
#pragma unroll
        for (int kc2 = 0; kc2 < 4; kc2++) {
            uint32_t pHi[4], pLo[4];
            split2(s[2*kc2][0],   s[2*kc2][1],   pHi[0], pLo[0]);
            split2(s[2*kc2][2],   s[2*kc2][3],   pHi[1], pLo[1]);
            split2(s[2*kc2+1][0], s[2*kc2+1][1], pHi[2], pLo[2]);
            split2(s[2*kc2+1][2], s[2*kc2+1][3], pHi[3], pLo[3]);
            const uint32_t vRowBase = vBase + (uint32_t)(kc2 * 16 * ROWB) + vRow4;
#pragma unroll
            for (int j2p = 0; j2p < 8; j2p++) {
                uint32_t vHi[4], vLo[4];
                const uint32_t bo = vRowBase + j2p * 32;
                ldsm_x4t(vHi, bo);
                ldsm_x4t(vLo, bo + SUBSZ);
                mma16816(o[2*j2p],   pHi, vHi);
                mma16816(o[2*j2p],   pHi, vLo);
                mma16816(o[2*j2p],   pLo, vHi);
                mma16816(o[2*j2p+1], pHi, vHi + 2);
                mma16816(o[2*j2p+1], pHi, vLo + 2);
                mma16816(o[2*j2p+1], pLo, vHi + 2);
            }
        }
    }

    // ---- epilogue ----
    {
        const float i0 = 1.0f / l0r, i1 = 1.0f / l1r;
        float* ob0 = O + ((size_t)(b * T_LEN + rG0) * NQ_H + qh) * D_DIM;
        float* ob1 = O + ((size_t)(b * T_LEN + rG1) * NQ_H + qh) * D_DIM;
#pragma unroll
        for (int j2 = 0; j2 < 16; j2++) {
            const int col = 8 * j2 + 2 * qc;
            *(float2*)(ob0 + col) = make_float2(o[j2][0] * i0, o[j2][1] * i0);
            *(float2*)(ob1 + col) = make_float2(o[j2][2] * i1, o[j2][3] * i1);
        }
    }
}

extern "C" void kernel_launch(void* const* d_in, const int* in_sizes, int n_in,
                              void* d_out, int out_size)
{
    const float* q   = (const float*)d_in[0];
    const float* k   = (const float*)d_in[1];
    const float* v   = (const float*)d_in[2];
    const int*   seg = (const int*)d_in[3];
    float*       out = (float*)d_out;

    const int B = in_sizes[0] / (T_LEN * NQ_H * D_DIM);

    dim3 pgrid(T_LEN, NKV_H, B);
    prep_kv<<<pgrid, 64>>>(k, v);

    cudaFuncSetAttribute(attn_fwd_mma, cudaFuncAttributeMaxDynamicSharedMemorySize, SMEM_TOTAL);
    dim3 grid(T_LEN / BM, NQ_H, B);
    attn_fwd_mma<<<grid, NTHREADS, SMEM_TOTAL>>>(q, seg, out);
}